// round 14
// baseline (speedup 1.0000x reference)
#include <cuda_runtime.h>
#include <cuda_fp16.h>
#include <cstdint>

#define B   128
#define H0  224
#define W0  224
#define C1  16
#define HP  56
#define C2  32
#define H2  28
#define W2  28
#define BN_EPS 1e-5f

#define NPIX1 ((double)B * 112.0 * 112.0)
#define NPIX2 ((double)B * H2 * W2)

// ---------------- scratch ----------------
__device__ __half  g_u1[B * HP * HP * C1];     // NHWC pooled conv1 raw, fp16
__device__ __half  g_y2[B * H2 * W2 * C2];     // NHWC conv2 raw, fp16
__device__ double  g_part1[32][C1][2];
__device__ double  g_part2[16][C2][2];
__device__ float   g_logit[B];

// ---------------- helpers ----------------
__device__ __forceinline__ void u4_to_f8(uint4 u, float* f) {
    float2 a;
    a = __half22float2(*reinterpret_cast<__half2*>(&u.x)); f[0] = a.x; f[1] = a.y;
    a = __half22float2(*reinterpret_cast<__half2*>(&u.y)); f[2] = a.x; f[3] = a.y;
    a = __half22float2(*reinterpret_cast<__half2*>(&u.z)); f[4] = a.x; f[5] = a.y;
    a = __half22float2(*reinterpret_cast<__half2*>(&u.w)); f[6] = a.x; f[7] = a.y;
}

// ---------------- kernels ----------------
__global__ void k_nop() {}

__global__ void k_zero() {
    double* p1 = &g_part1[0][0][0];
    double* p2 = &g_part2[0][0][0];
    for (int i = threadIdx.x; i < 32 * C1 * 2; i += blockDim.x) p1[i] = 0.0;
    for (int i = threadIdx.x; i < 16 * C2 * 2; i += blockDim.x) p2[i] = 0.0;
    if (threadIdx.x < B) g_logit[threadIdx.x] = 0.f;
}

// conv1(stride2,pad1; bias cancels in BN) + 2x2 maxpool + BN1 stats via HMMA.
// (R12 verified form: planar fp16 tile, permuted K with zero-weight pads.)
__global__ void __launch_bounds__(128) k_conv1pool(const float* __restrict__ x,
                                                   const float* __restrict__ w) {
    __shared__ __align__(16) __half tile[3 * 34 * 36];   // planar [ic][row][col]
    __shared__ __align__(16) __half wA[16 * 48];         // [ch][k'] permuted/padded
    __shared__ float sh_s[C1], sh_q[C1];

    int tid = threadIdx.x;
    int blk = blockIdx.x;                 // n*49 + bti*7 + btj
    int btj = blk % 7;
    int bti = (blk / 7) % 7;
    int n   = blk / 49;

    {
        uint4 z = make_uint4(0u, 0u, 0u, 0u);
        uint4* tz = reinterpret_cast<uint4*>(tile);
        for (int i = tid; i < 459; i += 128) tz[i] = z;
    }
    {
        int c  = tid & 15;
        int k0 = (tid >> 4) * 6;
#pragma unroll
        for (int u = 0; u < 6; u++) {
            int k  = k0 + u;
            int ic = k >> 4, r = k & 15, ky = r >> 2, slot = r & 3;
            float v = (slot > 0 && ky < 3) ? w[c * 27 + ic * 9 + ky * 3 + (slot - 1)] : 0.f;
            wA[c * 48 + k] = __float2half(v);
        }
    }
    if (tid < C1) { sh_s[tid] = 0.f; sh_q[tid] = 0.f; }
    __syncthreads();

    const int rowg0 = 32 * bti - 1;
    const int colg0 = 32 * btj - 4;
    {
        int quad = tid % 9;
        int rt   = tid / 9;
        for (int f = tid; f < 891; f += 128) {
            int ch = (rt >= 66) ? 2 : (rt >= 33 ? 1 : 0);
            int rr = rt - ch * 33;
            int rg = rowg0 + rr;
            int cg = colg0 + 4 * quad;
            if (rg >= 0 && cg >= 0) {
                float4 v = *reinterpret_cast<const float4*>(
                    x + ((n * 3 + ch) * H0 + rg) * W0 + cg);
                __half2 h01 = __floats2half2_rn(v.x, v.y);
                __half2 h23 = __floats2half2_rn(v.z, v.w);
                uint2 st;
                st.x = *reinterpret_cast<unsigned int*>(&h01);
                st.y = *reinterpret_cast<unsigned int*>(&h23);
                *reinterpret_cast<uint2*>(&tile[ch * 1224 + rr * 36 + 4 * quad]) = st;
            }
            quad += 2; rt += 14;
            if (quad >= 9) { quad -= 9; rt++; }
        }
    }
    __syncthreads();

    int lane = tid & 31;
    int warp = tid >> 5;
    int g = lane >> 2;
    int t = lane & 3;
    int g2 = g >> 2, g3 = g & 3;

    int coff = (t >> 1) * 36 + 2 * (t & 1) + 2;
    int gconst = 72 * g2 + 2 * g3;

    uint32_t af[3][4];
    {
        const uint32_t* wp = reinterpret_cast<const uint32_t*>(wA);
#pragma unroll
        for (int s = 0; s < 3; s++) {
            int kb = 16 * s + 2 * t;
            af[s][0] = wp[(g * 48 + kb) >> 1];
            af[s][1] = wp[((g + 8) * 48 + kb) >> 1];
            af[s][2] = wp[(g * 48 + kb + 8) >> 1];
            af[s][3] = wp[((g + 8) * 48 + kb + 8) >> 1];
        }
    }

    float s_lo = 0.f, q_lo = 0.f, s_hi = 0.f, q_hi = 0.f;

#pragma unroll 1
    for (int it = 0; it < 8; it++) {
        int tt   = warp + 4 * it;
        int trow = tt >> 2;
        int tq   = tt & 3;
        int base = 144 * trow + 8 * tq + gconst + coff;

        float d0 = 0.f, d1 = 0.f, d2 = 0.f, d3 = 0.f;
#pragma unroll
        for (int s = 0; s < 3; s++) {
            uint32_t b0 = *reinterpret_cast<const uint32_t*>(&tile[s * 1224 + base]);
            uint32_t b1 = *reinterpret_cast<const uint32_t*>(&tile[s * 1224 + base + 72]);
            asm volatile(
                "mma.sync.aligned.m16n8k16.row.col.f32.f16.f16.f32 "
                "{%0,%1,%2,%3}, {%4,%5,%6,%7}, {%8,%9}, {%0,%1,%2,%3};"
                : "+f"(d0), "+f"(d1), "+f"(d2), "+f"(d3)
                : "r"(af[s][0]), "r"(af[s][1]), "r"(af[s][2]), "r"(af[s][3]),
                  "r"(b0), "r"(b1));
        }

        s_lo += d0 + d1;  q_lo = fmaf(d0, d0, fmaf(d1, d1, q_lo));
        s_hi += d2 + d3;  q_hi = fmaf(d2, d2, fmaf(d3, d3, q_hi));

        float m0 = fmaxf(d0, d1);
        float m2 = fmaxf(d2, d3);
        m0 = fmaxf(m0, __shfl_xor_sync(0xffffffffu, m0, 2));
        m2 = fmaxf(m2, __shfl_xor_sync(0xffffffffu, m2, 2));
        if (t < 2) {
            int pr = 8 * bti + trow;
            int pc = 8 * btj + 2 * tq + t;
            __half* up = g_u1 + ((n * HP + pr) * HP + pc) * C1;
            up[g]     = __float2half(m0);
            up[g + 8] = __float2half(m2);
        }
    }

    s_lo += __shfl_xor_sync(0xffffffffu, s_lo, 1);
    s_lo += __shfl_xor_sync(0xffffffffu, s_lo, 2);
    q_lo += __shfl_xor_sync(0xffffffffu, q_lo, 1);
    q_lo += __shfl_xor_sync(0xffffffffu, q_lo, 2);
    s_hi += __shfl_xor_sync(0xffffffffu, s_hi, 1);
    s_hi += __shfl_xor_sync(0xffffffffu, s_hi, 2);
    q_hi += __shfl_xor_sync(0xffffffffu, q_hi, 1);
    q_hi += __shfl_xor_sync(0xffffffffu, q_hi, 2);
    if (t == 0) {
        atomicAdd(&sh_s[g], s_lo);     atomicAdd(&sh_q[g], q_lo);
        atomicAdd(&sh_s[g + 8], s_hi); atomicAdd(&sh_q[g + 8], q_hi);
    }
    __syncthreads();
    if (tid < C1) {
        int bin = blk & 31;
        atomicAdd(&g_part1[bin][tid][0], (double)sh_s[tid]);
        atomicAdd(&g_part1[bin][tid][1], (double)sh_q[tid]);
    }
}

// conv2(stride2,pad1) via HMMA with PREFETCHED taps: all 18 LDG.32 issued
// before any BN/MMA (MLP 2 -> 18). Warp = 8 linear pixels, 2 m-tiles.
__global__ void __launch_bounds__(128) k_conv2(const float* __restrict__ w,
                                               const float* __restrict__ g1,
                                               const float* __restrict__ b1) {
    __shared__ __align__(16) uint32_t wfragF[2 * 9 * 32 * 4]; // [m][tap][lane][r]
    __shared__ float sc1[C1], sh1[C1];
    __shared__ float s2s[C2], s2q[C2];

    int tid = threadIdx.x;
    if (tid < C1) {
        int c = tid;
        double s = 0.0, q = 0.0;
#pragma unroll
        for (int bb = 0; bb < 32; bb++) { s += g_part1[bb][c][0]; q += g_part1[bb][c][1]; }
        double mean = s / NPIX1;
        double var  = q / NPIX1 - mean * mean;
        float scale = g1[c] * (1.0f / sqrtf((float)var + BN_EPS));
        sc1[c] = scale;
        sh1[c] = b1[c] - (float)mean * scale;
    }
    if (tid < C2) { s2s[tid] = 0.f; s2q[tid] = 0.f; }

    // build per-lane A fragments: entry e = ((m*9+tap)*32+lane)*4 + r
    for (int e = tid; e < 2304; e += 128) {
        int r    = e & 3;
        int ln   = (e >> 2) & 31;
        int mt   = e >> 7;             // 0..17
        int tap  = mt % 9;
        int m    = mt / 9;
        int gg   = ln >> 2, tt = ln & 3;
        int row  = 16 * m + gg + ((r & 1) ? 8 : 0);
        int k0   = 2 * tt + ((r & 2) ? 8 : 0);
        __half2 h = __floats2half2_rn(w[row * 144 + k0 * 9 + tap],
                                      w[row * 144 + (k0 + 1) * 9 + tap]);
        wfragF[e] = *reinterpret_cast<uint32_t*>(&h);
    }
    __syncthreads();

    int lane = tid & 31;
    int warp = tid >> 5;
    int g = lane >> 2;
    int t = lane & 3;

    int tilebase = (blockIdx.x * 4 + warp) * 8;     // 8 pixels per warp
    int p   = tilebase + g;                          // this lane's pixel
    int n   = p / (H2 * W2);
    int rem = p - n * (H2 * W2);
    int ho  = rem / W2;
    int wo  = rem - ho * W2;

    // ---- prefetch all 9 taps (18 independent LDG.32) ----
    uint32_t vb0[9], vb1[9];
#pragma unroll
    for (int ky = 0; ky < 3; ky++) {
        int row = 2 * ho - 1 + ky;                   // <= 55 always
        const uint32_t* rowp = reinterpret_cast<const uint32_t*>(
            g_u1 + ((n * HP + row) * HP) * C1);
#pragma unroll
        for (int kx = 0; kx < 3; kx++) {
            int tap = ky * 3 + kx;
            int col = 2 * wo - 1 + kx;               // <= 55 always
            bool ok = (row >= 0) && (col >= 0);
            vb0[tap] = 0u; vb1[tap] = 0u;
            if (ok) {
                vb0[tap] = rowp[col * 8 + t];
                vb1[tap] = rowp[col * 8 + t + 4];
            }
        }
    }

    // lane BN constants: channels (2t,2t+1) and (2t+8,2t+9)
    __half2 scA = __floats2half2_rn(sc1[2 * t],     sc1[2 * t + 1]);
    __half2 shA = __floats2half2_rn(sh1[2 * t],     sh1[2 * t + 1]);
    __half2 scB = __floats2half2_rn(sc1[2 * t + 8], sc1[2 * t + 9]);
    __half2 shB = __floats2half2_rn(sh1[2 * t + 8], sh1[2 * t + 9]);
    __half2 z2  = __float2half2_rn(0.f);

    float d0[4] = {0.f, 0.f, 0.f, 0.f};
    float d1m[4] = {0.f, 0.f, 0.f, 0.f};

#pragma unroll
    for (int tap = 0; tap < 9; tap++) {
        uint32_t b0 = 0u, b1 = 0u;
        if (vb0[tap] | vb1[tap]) {                   // pad stays zero either way
            __half2 h0 = __hmax2(__hfma2(*reinterpret_cast<__half2*>(&vb0[tap]), scA, shA), z2);
            __half2 h1 = __hmax2(__hfma2(*reinterpret_cast<__half2*>(&vb1[tap]), scB, shB), z2);
            b0 = *reinterpret_cast<uint32_t*>(&h0);
            b1 = *reinterpret_cast<uint32_t*>(&h1);
        }
        uint4 A0 = *reinterpret_cast<const uint4*>(&wfragF[(tap * 32 + lane) * 4]);
        uint4 A1 = *reinterpret_cast<const uint4*>(&wfragF[((9 + tap) * 32 + lane) * 4]);
        asm volatile(
            "mma.sync.aligned.m16n8k16.row.col.f32.f16.f16.f32 "
            "{%0,%1,%2,%3}, {%4,%5,%6,%7}, {%8,%9}, {%0,%1,%2,%3};"
            : "+f"(d0[0]), "+f"(d0[1]), "+f"(d0[2]), "+f"(d0[3])
            : "r"(A0.x), "r"(A0.y), "r"(A0.z), "r"(A0.w), "r"(b0), "r"(b1));
        asm volatile(
            "mma.sync.aligned.m16n8k16.row.col.f32.f16.f16.f32 "
            "{%0,%1,%2,%3}, {%4,%5,%6,%7}, {%8,%9}, {%0,%1,%2,%3};"
            : "+f"(d1m[0]), "+f"(d1m[1]), "+f"(d1m[2]), "+f"(d1m[3])
            : "r"(A1.x), "r"(A1.y), "r"(A1.z), "r"(A1.w), "r"(b0), "r"(b1));
    }

    // WAIT: BN of a zeroed pad load gives relu(shift) != 0 — must zero by
    // predicate, not by value. Recompute masks exactly as the loads did.
    // (Handled above: vb==0 check is wrong only if a REAL tap reads exactly
    //  0-bits AND shift>0. Real taps: relu(shA) applied to true zeros is
    //  CORRECT (padding in h-space is relu(0*scale+shift)? No — true
    //  zero-padding of conv2 input h is h=0, which is relu-consistent.)
    // Pad taps (row<0/col<0) must contribute h=0: achieved since vb==0 path
    // leaves b=0. Real taps with vb==0 bits: h = relu(0*sc+sh) may be nonzero
    // — but vb==0 means u1 stored -0.0/0.0 halves; BN of true value 0 is
    // relu(sh), which the branch skips. This is a (2^-24-probability per
    // half) edge ONLY when stored value is exactly +0.0 in BOTH words; u1
    // holds pre-BN conv outputs (continuous), so measure-zero risk accepted
    // for this round pending rel_err check.

    // store: lane owns out ch {g, g+8, g+16, g+24} at pixels tilebase+2t, +2t+1
    {
        __half* y0 = g_y2 + (long)(tilebase + 2 * t) * C2;
        __half* y1 = y0 + C2;
        y0[g]      = __float2half(d0[0]);  y1[g]      = __float2half(d0[1]);
        y0[g + 8]  = __float2half(d0[2]);  y1[g + 8]  = __float2half(d0[3]);
        y0[g + 16] = __float2half(d1m[0]); y1[g + 16] = __float2half(d1m[1]);
        y0[g + 24] = __float2half(d1m[2]); y1[g + 24] = __float2half(d1m[3]);
    }

    // BN2 stats: reduce over t lanes (bits 0,1), channels per (m, lo/hi)
#pragma unroll
    for (int m = 0; m < 2; m++) {
        const float* dd = (m == 0) ? d0 : d1m;
        float sl = dd[0] + dd[1];
        float ql = fmaf(dd[0], dd[0], dd[1] * dd[1]);
        float sh = dd[2] + dd[3];
        float qh = fmaf(dd[2], dd[2], dd[3] * dd[3]);
        sl += __shfl_xor_sync(0xffffffffu, sl, 1);
        sl += __shfl_xor_sync(0xffffffffu, sl, 2);
        ql += __shfl_xor_sync(0xffffffffu, ql, 1);
        ql += __shfl_xor_sync(0xffffffffu, ql, 2);
        sh += __shfl_xor_sync(0xffffffffu, sh, 1);
        sh += __shfl_xor_sync(0xffffffffu, sh, 2);
        qh += __shfl_xor_sync(0xffffffffu, qh, 1);
        qh += __shfl_xor_sync(0xffffffffu, qh, 2);
        if (t == 0) {
            atomicAdd(&s2s[16 * m + g], sl);     atomicAdd(&s2q[16 * m + g], ql);
            atomicAdd(&s2s[16 * m + g + 8], sh); atomicAdd(&s2q[16 * m + g + 8], qh);
        }
    }
    __syncthreads();
    if (tid < C2) {
        int bin = blockIdx.x & 15;
        atomicAdd(&g_part2[bin][tid][0], (double)s2s[tid]);
        atomicAdd(&g_part2[bin][tid][1], (double)s2q[tid]);
    }
}

// BN2+ReLU+avg+fc partials: 2 blocks/sample -> atomic into g_logit
__global__ void __launch_bounds__(256) k_final2(const float* __restrict__ g2,
                                                const float* __restrict__ b2,
                                                const float* __restrict__ fcw) {
    __shared__ float ssc[C2], ssh[C2], sw[C2];
    __shared__ float red[256];
    int tid = threadIdx.x;
    if (tid < C2) {
        double s = 0.0, q = 0.0;
#pragma unroll
        for (int bb = 0; bb < 16; bb++) { s += g_part2[bb][tid][0]; q += g_part2[bb][tid][1]; }
        double mean = s / NPIX2;
        double var  = q / NPIX2 - mean * mean;
        float scale = g2[tid] * (1.0f / sqrtf((float)var + BN_EPS));
        ssc[tid] = scale;
        ssh[tid] = b2[tid] - (float)mean * scale;
        sw[tid]  = fcw[tid];
    }
    __syncthreads();

    int cg = (tid & 3) * 8;
    float rsc[8], rsh[8], rw[8];
#pragma unroll
    for (int k = 0; k < 8; k++) { rsc[k] = ssc[cg + k]; rsh[k] = ssh[cg + k]; rw[k] = sw[cg + k]; }

    int n     = blockIdx.x >> 1;
    int chunk = blockIdx.x & 1;
    const uint4* p = reinterpret_cast<const uint4*>(g_y2 + n * H2 * W2 * C2);
    const int NV = H2 * W2 * C2 / 8;
    int start = chunk * (NV / 2);
    float acc = 0.f;
    for (int i = start + tid; i < start + NV / 2; i += 256) {
        float f[8];
        u4_to_f8(p[i], f);
#pragma unroll
        for (int k = 0; k < 8; k++) {
            float e = fmaxf(fmaf(rsc[k], f[k], rsh[k]), 0.f);
            acc = fmaf(rw[k], e, acc);
        }
    }
    red[tid] = acc;
    __syncthreads();
    for (int o = 128; o > 0; o >>= 1) {
        if (tid < o) red[tid] += red[tid + o];
        __syncthreads();
    }
    if (tid == 0) atomicAdd(&g_logit[n], red[0]);
}

__global__ void k_cos(const float* __restrict__ fcb, float* __restrict__ out) {
    int n = threadIdx.x;
    if (n < B) {
        float logit = g_logit[n] / (float)(H2 * W2) + fcb[0];
        float pr = cosf(logit);
        out[2 * n]     = pr;
        out[2 * n + 1] = 1.f - pr;
    }
}

// ---------------- launcher ----------------
extern "C" void kernel_launch(void* const* d_in, const int* in_sizes, int n_in,
                              void* d_out, int out_size) {
    const float* x    = (const float*)d_in[0];
    const float* c1w  = (const float*)d_in[1];
    const float* bn1g = (const float*)d_in[3];
    const float* bn1b = (const float*)d_in[4];
    const float* c2w  = (const float*)d_in[5];
    const float* bn2g = (const float*)d_in[7];
    const float* bn2b = (const float*)d_in[8];
    const float* fcw  = (const float*)d_in[9];
    const float* fcb  = (const float*)d_in[10];
    float* out = (float*)d_out;

    k_zero<<<1, 256>>>();
    k_conv1pool<<<B * 49, 128>>>(x, c1w);                    // 6272 blocks
    k_nop<<<1, 32>>>();                                      // conv2 -> capture slot 4
    k_conv2<<<(B * H2 * W2) / 32, 128>>>(c2w, bn1g, bn1b);   // 3136 blocks
    k_final2<<<B * 2, 256>>>(bn2g, bn2b, fcw);
    k_cos<<<1, 128>>>(fcb, out);
}

// round 15
// speedup vs baseline: 1.3414x; 1.3414x over previous
#include <cuda_runtime.h>
#include <cuda_fp16.h>
#include <cstdint>

#define B   128
#define H0  224
#define W0  224
#define C1  16
#define HP  56
#define C2  32
#define H2  28
#define W2  28
#define BN_EPS 1e-5f

#define NPIX1 ((double)B * 112.0 * 112.0)
#define NPIX2 ((double)B * H2 * W2)

// ---------------- scratch ----------------
__device__ __half  g_u1[B * HP * HP * C1];     // NHWC pooled conv1 raw, fp16
__device__ __half  g_y2[B * H2 * W2 * C2];     // NHWC conv2 raw, fp16
__device__ double  g_part1[32][C1][2];
__device__ double  g_part2[16][C2][2];
__device__ float   g_bnp2f[2 * C2];            // BN2 scale[32], shift[32]
__device__ float   g_logit[B];

// ---------------- helpers ----------------
__device__ __forceinline__ void u4_to_f8(uint4 u, float* f) {
    float2 a;
    a = __half22float2(*reinterpret_cast<__half2*>(&u.x)); f[0] = a.x; f[1] = a.y;
    a = __half22float2(*reinterpret_cast<__half2*>(&u.y)); f[2] = a.x; f[3] = a.y;
    a = __half22float2(*reinterpret_cast<__half2*>(&u.z)); f[4] = a.x; f[5] = a.y;
    a = __half22float2(*reinterpret_cast<__half2*>(&u.w)); f[6] = a.x; f[7] = a.y;
}

// ---------------- kernels ----------------
__global__ void k_nop() {}

__global__ void k_zero() {
    double* p1 = &g_part1[0][0][0];
    double* p2 = &g_part2[0][0][0];
    for (int i = threadIdx.x; i < 32 * C1 * 2; i += blockDim.x) p1[i] = 0.0;
    for (int i = threadIdx.x; i < 16 * C2 * 2; i += blockDim.x) p2[i] = 0.0;
    if (threadIdx.x < B) g_logit[threadIdx.x] = 0.f;
}

// conv1(stride2,pad1; bias cancels in BN) + 2x2 maxpool + BN1 stats via HMMA.
// (R12 verified form: planar fp16 tile, permuted K with zero-weight pads.)
__global__ void __launch_bounds__(128) k_conv1pool(const float* __restrict__ x,
                                                   const float* __restrict__ w) {
    __shared__ __align__(16) __half tile[3 * 34 * 36];   // planar [ic][row][col]
    __shared__ __align__(16) __half wA[16 * 48];         // [ch][k'] permuted/padded
    __shared__ float sh_s[C1], sh_q[C1];

    int tid = threadIdx.x;
    int blk = blockIdx.x;                 // n*49 + bti*7 + btj
    int btj = blk % 7;
    int bti = (blk / 7) % 7;
    int n   = blk / 49;

    {
        uint4 z = make_uint4(0u, 0u, 0u, 0u);
        uint4* tz = reinterpret_cast<uint4*>(tile);
        for (int i = tid; i < 459; i += 128) tz[i] = z;
    }
    {
        int c  = tid & 15;
        int k0 = (tid >> 4) * 6;
#pragma unroll
        for (int u = 0; u < 6; u++) {
            int k  = k0 + u;
            int ic = k >> 4, r = k & 15, ky = r >> 2, slot = r & 3;
            float v = (slot > 0 && ky < 3) ? w[c * 27 + ic * 9 + ky * 3 + (slot - 1)] : 0.f;
            wA[c * 48 + k] = __float2half(v);
        }
    }
    if (tid < C1) { sh_s[tid] = 0.f; sh_q[tid] = 0.f; }
    __syncthreads();

    const int rowg0 = 32 * bti - 1;
    const int colg0 = 32 * btj - 4;
    {
        int quad = tid % 9;
        int rt   = tid / 9;
        for (int f = tid; f < 891; f += 128) {
            int ch = (rt >= 66) ? 2 : (rt >= 33 ? 1 : 0);
            int rr = rt - ch * 33;
            int rg = rowg0 + rr;
            int cg = colg0 + 4 * quad;
            if (rg >= 0 && cg >= 0) {
                float4 v = *reinterpret_cast<const float4*>(
                    x + ((n * 3 + ch) * H0 + rg) * W0 + cg);
                __half2 h01 = __floats2half2_rn(v.x, v.y);
                __half2 h23 = __floats2half2_rn(v.z, v.w);
                uint2 st;
                st.x = *reinterpret_cast<unsigned int*>(&h01);
                st.y = *reinterpret_cast<unsigned int*>(&h23);
                *reinterpret_cast<uint2*>(&tile[ch * 1224 + rr * 36 + 4 * quad]) = st;
            }
            quad += 2; rt += 14;
            if (quad >= 9) { quad -= 9; rt++; }
        }
    }
    __syncthreads();

    int lane = tid & 31;
    int warp = tid >> 5;
    int g = lane >> 2;
    int t = lane & 3;
    int g2 = g >> 2, g3 = g & 3;

    int coff = (t >> 1) * 36 + 2 * (t & 1) + 2;
    int gconst = 72 * g2 + 2 * g3;

    uint32_t af[3][4];
    {
        const uint32_t* wp = reinterpret_cast<const uint32_t*>(wA);
#pragma unroll
        for (int s = 0; s < 3; s++) {
            int kb = 16 * s + 2 * t;
            af[s][0] = wp[(g * 48 + kb) >> 1];
            af[s][1] = wp[((g + 8) * 48 + kb) >> 1];
            af[s][2] = wp[(g * 48 + kb + 8) >> 1];
            af[s][3] = wp[((g + 8) * 48 + kb + 8) >> 1];
        }
    }

    float s_lo = 0.f, q_lo = 0.f, s_hi = 0.f, q_hi = 0.f;

#pragma unroll 1
    for (int it = 0; it < 8; it++) {
        int tt   = warp + 4 * it;
        int trow = tt >> 2;
        int tq   = tt & 3;
        int base = 144 * trow + 8 * tq + gconst + coff;

        float d0 = 0.f, d1 = 0.f, d2 = 0.f, d3 = 0.f;
#pragma unroll
        for (int s = 0; s < 3; s++) {
            uint32_t b0 = *reinterpret_cast<const uint32_t*>(&tile[s * 1224 + base]);
            uint32_t b1 = *reinterpret_cast<const uint32_t*>(&tile[s * 1224 + base + 72]);
            asm volatile(
                "mma.sync.aligned.m16n8k16.row.col.f32.f16.f16.f32 "
                "{%0,%1,%2,%3}, {%4,%5,%6,%7}, {%8,%9}, {%0,%1,%2,%3};"
                : "+f"(d0), "+f"(d1), "+f"(d2), "+f"(d3)
                : "r"(af[s][0]), "r"(af[s][1]), "r"(af[s][2]), "r"(af[s][3]),
                  "r"(b0), "r"(b1));
        }

        s_lo += d0 + d1;  q_lo = fmaf(d0, d0, fmaf(d1, d1, q_lo));
        s_hi += d2 + d3;  q_hi = fmaf(d2, d2, fmaf(d3, d3, q_hi));

        float m0 = fmaxf(d0, d1);
        float m2 = fmaxf(d2, d3);
        m0 = fmaxf(m0, __shfl_xor_sync(0xffffffffu, m0, 2));
        m2 = fmaxf(m2, __shfl_xor_sync(0xffffffffu, m2, 2));
        if (t < 2) {
            int pr = 8 * bti + trow;
            int pc = 8 * btj + 2 * tq + t;
            __half* up = g_u1 + ((n * HP + pr) * HP + pc) * C1;
            up[g]     = __float2half(m0);
            up[g + 8] = __float2half(m2);
        }
    }

    s_lo += __shfl_xor_sync(0xffffffffu, s_lo, 1);
    s_lo += __shfl_xor_sync(0xffffffffu, s_lo, 2);
    q_lo += __shfl_xor_sync(0xffffffffu, q_lo, 1);
    q_lo += __shfl_xor_sync(0xffffffffu, q_lo, 2);
    s_hi += __shfl_xor_sync(0xffffffffu, s_hi, 1);
    s_hi += __shfl_xor_sync(0xffffffffu, s_hi, 2);
    q_hi += __shfl_xor_sync(0xffffffffu, q_hi, 1);
    q_hi += __shfl_xor_sync(0xffffffffu, q_hi, 2);
    if (t == 0) {
        atomicAdd(&sh_s[g], s_lo);     atomicAdd(&sh_q[g], q_lo);
        atomicAdd(&sh_s[g + 8], s_hi); atomicAdd(&sh_q[g + 8], q_hi);
    }
    __syncthreads();
    if (tid < C1) {
        int bin = blk & 31;
        atomicAdd(&g_part1[bin][tid][0], (double)sh_s[tid]);
        atomicAdd(&g_part1[bin][tid][1], (double)sh_q[tid]);
    }
}

// conv2(stride2,pad1) via HMMA (R13 exact form): K-step = one tap's 16 NHWC
// channels; BN1+ReLU in half2 registers; pad taps zeroed. Warp = 8 pixels.
__global__ void __launch_bounds__(128) k_conv2(const float* __restrict__ w,
                                               const float* __restrict__ g1,
                                               const float* __restrict__ b1) {
    __shared__ __align__(16) uint32_t wfragF[2 * 9 * 32 * 4]; // [m][tap][lane][r]
    __shared__ float sc1[C1], sh1[C1];
    __shared__ float s2s[C2], s2q[C2];

    int tid = threadIdx.x;
    if (tid < C1) {
        int c = tid;
        double s = 0.0, q = 0.0;
#pragma unroll
        for (int bb = 0; bb < 32; bb++) { s += g_part1[bb][c][0]; q += g_part1[bb][c][1]; }
        double mean = s / NPIX1;
        double var  = q / NPIX1 - mean * mean;
        float scale = g1[c] * (1.0f / sqrtf((float)var + BN_EPS));
        sc1[c] = scale;
        sh1[c] = b1[c] - (float)mean * scale;
    }
    if (tid < C2) { s2s[tid] = 0.f; s2q[tid] = 0.f; }

    // build per-lane A fragments: entry e = ((m*9+tap)*32+lane)*4 + r
    for (int e = tid; e < 2304; e += 128) {
        int r    = e & 3;
        int ln   = (e >> 2) & 31;
        int mt   = e >> 7;             // 0..17
        int tap  = mt % 9;
        int m    = mt / 9;
        int gg   = ln >> 2, tt = ln & 3;
        int row  = 16 * m + gg + ((r & 1) ? 8 : 0);
        int k0   = 2 * tt + ((r & 2) ? 8 : 0);
        __half2 h = __floats2half2_rn(w[row * 144 + k0 * 9 + tap],
                                      w[row * 144 + (k0 + 1) * 9 + tap]);
        wfragF[e] = *reinterpret_cast<uint32_t*>(&h);
    }
    __syncthreads();

    int lane = tid & 31;
    int warp = tid >> 5;
    int g = lane >> 2;
    int t = lane & 3;

    int tilebase = (blockIdx.x * 4 + warp) * 8;     // 8 pixels per warp
    int p   = tilebase + g;                          // this lane's pixel
    int n   = p / (H2 * W2);
    int rem = p - n * (H2 * W2);
    int ho  = rem / W2;
    int wo  = rem - ho * W2;

    // lane BN constants: channels (2t,2t+1) and (2t+8,2t+9)
    __half2 scA = __floats2half2_rn(sc1[2 * t],     sc1[2 * t + 1]);
    __half2 shA = __floats2half2_rn(sh1[2 * t],     sh1[2 * t + 1]);
    __half2 scB = __floats2half2_rn(sc1[2 * t + 8], sc1[2 * t + 9]);
    __half2 shB = __floats2half2_rn(sh1[2 * t + 8], sh1[2 * t + 9]);
    __half2 z2  = __float2half2_rn(0.f);

    float d0[4] = {0.f, 0.f, 0.f, 0.f};
    float d1m[4] = {0.f, 0.f, 0.f, 0.f};

#pragma unroll
    for (int ky = 0; ky < 3; ky++) {
        int row = 2 * ho - 1 + ky;                   // <= 55 always
        bool rok = (row >= 0);
        const uint32_t* rowp = reinterpret_cast<const uint32_t*>(
            g_u1 + ((n * HP + row) * HP) * C1);
#pragma unroll
        for (int kx = 0; kx < 3; kx++) {
            int col = 2 * wo - 1 + kx;               // <= 55 always
            uint32_t b0 = 0u, b1 = 0u;
            if (rok && col >= 0) {
                uint32_t v0 = rowp[col * 8 + t];
                uint32_t v1 = rowp[col * 8 + t + 4];
                __half2 h0 = __hmax2(__hfma2(*reinterpret_cast<__half2*>(&v0), scA, shA), z2);
                __half2 h1 = __hmax2(__hfma2(*reinterpret_cast<__half2*>(&v1), scB, shB), z2);
                b0 = *reinterpret_cast<uint32_t*>(&h0);
                b1 = *reinterpret_cast<uint32_t*>(&h1);
            }
            int tap = ky * 3 + kx;
            uint4 A0 = *reinterpret_cast<const uint4*>(&wfragF[(tap * 32 + lane) * 4]);
            uint4 A1 = *reinterpret_cast<const uint4*>(&wfragF[((9 + tap) * 32 + lane) * 4]);
            asm volatile(
                "mma.sync.aligned.m16n8k16.row.col.f32.f16.f16.f32 "
                "{%0,%1,%2,%3}, {%4,%5,%6,%7}, {%8,%9}, {%0,%1,%2,%3};"
                : "+f"(d0[0]), "+f"(d0[1]), "+f"(d0[2]), "+f"(d0[3])
                : "r"(A0.x), "r"(A0.y), "r"(A0.z), "r"(A0.w), "r"(b0), "r"(b1));
            asm volatile(
                "mma.sync.aligned.m16n8k16.row.col.f32.f16.f16.f32 "
                "{%0,%1,%2,%3}, {%4,%5,%6,%7}, {%8,%9}, {%0,%1,%2,%3};"
                : "+f"(d1m[0]), "+f"(d1m[1]), "+f"(d1m[2]), "+f"(d1m[3])
                : "r"(A1.x), "r"(A1.y), "r"(A1.z), "r"(A1.w), "r"(b0), "r"(b1));
        }
    }

    // store: lane owns out ch {g, g+8, g+16, g+24} at pixels tilebase+2t, +2t+1
    {
        __half* y0 = g_y2 + (long)(tilebase + 2 * t) * C2;
        __half* y1 = y0 + C2;
        y0[g]      = __float2half(d0[0]);  y1[g]      = __float2half(d0[1]);
        y0[g + 8]  = __float2half(d0[2]);  y1[g + 8]  = __float2half(d0[3]);
        y0[g + 16] = __float2half(d1m[0]); y1[g + 16] = __float2half(d1m[1]);
        y0[g + 24] = __float2half(d1m[2]); y1[g + 24] = __float2half(d1m[3]);
    }

    // BN2 stats: reduce over t lanes (bits 0,1), channels per (m, lo/hi)
#pragma unroll
    for (int m = 0; m < 2; m++) {
        const float* dd = (m == 0) ? d0 : d1m;
        float sl = dd[0] + dd[1];
        float ql = fmaf(dd[0], dd[0], dd[1] * dd[1]);
        float sh = dd[2] + dd[3];
        float qh = fmaf(dd[2], dd[2], dd[3] * dd[3]);
        sl += __shfl_xor_sync(0xffffffffu, sl, 1);
        sl += __shfl_xor_sync(0xffffffffu, sl, 2);
        ql += __shfl_xor_sync(0xffffffffu, ql, 1);
        ql += __shfl_xor_sync(0xffffffffu, ql, 2);
        sh += __shfl_xor_sync(0xffffffffu, sh, 1);
        sh += __shfl_xor_sync(0xffffffffu, sh, 2);
        qh += __shfl_xor_sync(0xffffffffu, qh, 1);
        qh += __shfl_xor_sync(0xffffffffu, qh, 2);
        if (t == 0) {
            atomicAdd(&s2s[16 * m + g], sl);     atomicAdd(&s2q[16 * m + g], ql);
            atomicAdd(&s2s[16 * m + g + 8], sh); atomicAdd(&s2q[16 * m + g + 8], qh);
        }
    }
    __syncthreads();
    if (tid < C2) {
        int bin = blockIdx.x & 15;
        atomicAdd(&g_part2[bin][tid][0], (double)s2s[tid]);
        atomicAdd(&g_part2[bin][tid][1], (double)s2q[tid]);
    }
}

// BN2 params once (was replicated in 256 final2 blocks)
__global__ void k_bn2p(const float* __restrict__ g2, const float* __restrict__ b2) {
    int c = threadIdx.x;
    if (c < C2) {
        double s = 0.0, q = 0.0;
#pragma unroll
        for (int bb = 0; bb < 16; bb++) { s += g_part2[bb][c][0]; q += g_part2[bb][c][1]; }
        double mean = s / NPIX2;
        double var  = q / NPIX2 - mean * mean;
        float scale = g2[c] * (1.0f / sqrtf((float)var + BN_EPS));
        g_bnp2f[c]      = scale;
        g_bnp2f[C2 + c] = b2[c] - (float)mean * scale;
    }
}

// BN2+ReLU+avg+fc partials: 2 blocks/sample -> atomic into g_logit
__global__ void __launch_bounds__(256) k_final2(const float* __restrict__ fcw) {
    __shared__ float ssc[C2], ssh[C2], sw[C2];
    __shared__ float red[256];
    int tid = threadIdx.x;
    if (tid < C2) {
        ssc[tid] = g_bnp2f[tid];
        ssh[tid] = g_bnp2f[C2 + tid];
        sw[tid]  = fcw[tid];
    }
    __syncthreads();

    int cg = (tid & 3) * 8;
    float rsc[8], rsh[8], rw[8];
#pragma unroll
    for (int k = 0; k < 8; k++) { rsc[k] = ssc[cg + k]; rsh[k] = ssh[cg + k]; rw[k] = sw[cg + k]; }

    int n     = blockIdx.x >> 1;
    int chunk = blockIdx.x & 1;
    const uint4* p = reinterpret_cast<const uint4*>(g_y2 + n * H2 * W2 * C2);
    const int NV = H2 * W2 * C2 / 8;
    int start = chunk * (NV / 2);
    float acc = 0.f;
    for (int i = start + tid; i < start + NV / 2; i += 256) {
        float f[8];
        u4_to_f8(p[i], f);
#pragma unroll
        for (int k = 0; k < 8; k++) {
            float e = fmaxf(fmaf(rsc[k], f[k], rsh[k]), 0.f);
            acc = fmaf(rw[k], e, acc);
        }
    }
    red[tid] = acc;
    __syncthreads();
    for (int o = 128; o > 0; o >>= 1) {
        if (tid < o) red[tid] += red[tid + o];
        __syncthreads();
    }
    if (tid == 0) atomicAdd(&g_logit[n], red[0]);
}

__global__ void k_cos(const float* __restrict__ fcb, float* __restrict__ out) {
    int n = threadIdx.x;
    if (n < B) {
        float logit = g_logit[n] / (float)(H2 * W2) + fcb[0];
        float pr = cosf(logit);
        out[2 * n]     = pr;
        out[2 * n + 1] = 1.f - pr;
    }
}

// ---------------- launcher ----------------
extern "C" void kernel_launch(void* const* d_in, const int* in_sizes, int n_in,
                              void* d_out, int out_size) {
    const float* x    = (const float*)d_in[0];
    const float* c1w  = (const float*)d_in[1];
    const float* bn1g = (const float*)d_in[3];
    const float* bn1b = (const float*)d_in[4];
    const float* c2w  = (const float*)d_in[5];
    const float* bn2g = (const float*)d_in[7];
    const float* bn2b = (const float*)d_in[8];
    const float* fcw  = (const float*)d_in[9];
    const float* fcb  = (const float*)d_in[10];
    float* out = (float*)d_out;

    k_zero<<<1, 256>>>();
    k_nop<<<1, 32>>>();
    k_nop<<<1, 32>>>();                                      // conv1 -> capture slot 4
    k_conv1pool<<<B * 49, 128>>>(x, c1w);                    // 6272 blocks
    k_conv2<<<(B * H2 * W2) / 32, 128>>>(c2w, bn1g, bn1b);   // 3136 blocks
    k_bn2p<<<1, 32>>>(bn2g, bn2b);
    k_final2<<<B * 2, 256>>>(fcw);
    k_cos<<<1, 128>>>(fcb, out);
}

// round 16
// speedup vs baseline: 1.4734x; 1.0984x over previous
#include <cuda_runtime.h>
#include <cuda_fp16.h>
#include <cstdint>

#define B   128
#define H0  224
#define W0  224
#define C1  16
#define HP  56
#define C2  32
#define H2  28
#define W2  28
#define BN_EPS 1e-5f

#define NPIX1 ((double)B * 112.0 * 112.0)
#define NPIX2 ((double)B * H2 * W2)

// ---------------- scratch ----------------
// Zero-invariant: device globals start zeroed (module load); k_coszero re-zeroes
// g_part1/g_part2/g_logit at the END of every kernel_launch call, so each call
// (correctness, capture, every replay) begins from the same state.
__device__ __half  g_u1[B * HP * HP * C1];     // NHWC pooled conv1 raw, fp16
__device__ __half  g_y2[B * H2 * W2 * C2];     // NHWC conv2 raw, fp16
__device__ double  g_part1[32][C1][2];
__device__ double  g_part2[16][C2][2];
__device__ float   g_logit[B];

// ---------------- helpers ----------------
__device__ __forceinline__ void u4_to_f8(uint4 u, float* f) {
    float2 a;
    a = __half22float2(*reinterpret_cast<__half2*>(&u.x)); f[0] = a.x; f[1] = a.y;
    a = __half22float2(*reinterpret_cast<__half2*>(&u.y)); f[2] = a.x; f[3] = a.y;
    a = __half22float2(*reinterpret_cast<__half2*>(&u.z)); f[4] = a.x; f[5] = a.y;
    a = __half22float2(*reinterpret_cast<__half2*>(&u.w)); f[6] = a.x; f[7] = a.y;
}

// conv1(stride2,pad1; bias cancels in BN) + 2x2 maxpool + BN1 stats via HMMA.
// (R12/R13 verified form: planar fp16 tile, permuted K with zero-weight pads.)
__global__ void __launch_bounds__(128) k_conv1pool(const float* __restrict__ x,
                                                   const float* __restrict__ w) {
    __shared__ __align__(16) __half tile[3 * 34 * 36];   // planar [ic][row][col]
    __shared__ __align__(16) __half wA[16 * 48];         // [ch][k'] permuted/padded
    __shared__ float sh_s[C1], sh_q[C1];

    int tid = threadIdx.x;
    int blk = blockIdx.x;                 // n*49 + bti*7 + btj
    int btj = blk % 7;
    int bti = (blk / 7) % 7;
    int n   = blk / 49;

    {
        uint4 z = make_uint4(0u, 0u, 0u, 0u);
        uint4* tz = reinterpret_cast<uint4*>(tile);
        for (int i = tid; i < 459; i += 128) tz[i] = z;
    }
    {
        int c  = tid & 15;
        int k0 = (tid >> 4) * 6;
#pragma unroll
        for (int u = 0; u < 6; u++) {
            int k  = k0 + u;
            int ic = k >> 4, r = k & 15, ky = r >> 2, slot = r & 3;
            float v = (slot > 0 && ky < 3) ? w[c * 27 + ic * 9 + ky * 3 + (slot - 1)] : 0.f;
            wA[c * 48 + k] = __float2half(v);
        }
    }
    if (tid < C1) { sh_s[tid] = 0.f; sh_q[tid] = 0.f; }
    __syncthreads();

    const int rowg0 = 32 * bti - 1;
    const int colg0 = 32 * btj - 4;
    {
        int quad = tid % 9;
        int rt   = tid / 9;
        for (int f = tid; f < 891; f += 128) {
            int ch = (rt >= 66) ? 2 : (rt >= 33 ? 1 : 0);
            int rr = rt - ch * 33;
            int rg = rowg0 + rr;
            int cg = colg0 + 4 * quad;
            if (rg >= 0 && cg >= 0) {
                float4 v = *reinterpret_cast<const float4*>(
                    x + ((n * 3 + ch) * H0 + rg) * W0 + cg);
                __half2 h01 = __floats2half2_rn(v.x, v.y);
                __half2 h23 = __floats2half2_rn(v.z, v.w);
                uint2 st;
                st.x = *reinterpret_cast<unsigned int*>(&h01);
                st.y = *reinterpret_cast<unsigned int*>(&h23);
                *reinterpret_cast<uint2*>(&tile[ch * 1224 + rr * 36 + 4 * quad]) = st;
            }
            quad += 2; rt += 14;
            if (quad >= 9) { quad -= 9; rt++; }
        }
    }
    __syncthreads();

    int lane = tid & 31;
    int warp = tid >> 5;
    int g = lane >> 2;
    int t = lane & 3;
    int g2 = g >> 2, g3 = g & 3;

    int coff = (t >> 1) * 36 + 2 * (t & 1) + 2;
    int gconst = 72 * g2 + 2 * g3;

    uint32_t af[3][4];
    {
        const uint32_t* wp = reinterpret_cast<const uint32_t*>(wA);
#pragma unroll
        for (int s = 0; s < 3; s++) {
            int kb = 16 * s + 2 * t;
            af[s][0] = wp[(g * 48 + kb) >> 1];
            af[s][1] = wp[((g + 8) * 48 + kb) >> 1];
            af[s][2] = wp[(g * 48 + kb + 8) >> 1];
            af[s][3] = wp[((g + 8) * 48 + kb + 8) >> 1];
        }
    }

    float s_lo = 0.f, q_lo = 0.f, s_hi = 0.f, q_hi = 0.f;

#pragma unroll 1
    for (int it = 0; it < 8; it++) {
        int tt   = warp + 4 * it;
        int trow = tt >> 2;
        int tq   = tt & 3;
        int base = 144 * trow + 8 * tq + gconst + coff;

        float d0 = 0.f, d1 = 0.f, d2 = 0.f, d3 = 0.f;
#pragma unroll
        for (int s = 0; s < 3; s++) {
            uint32_t b0 = *reinterpret_cast<const uint32_t*>(&tile[s * 1224 + base]);
            uint32_t b1 = *reinterpret_cast<const uint32_t*>(&tile[s * 1224 + base + 72]);
            asm volatile(
                "mma.sync.aligned.m16n8k16.row.col.f32.f16.f16.f32 "
                "{%0,%1,%2,%3}, {%4,%5,%6,%7}, {%8,%9}, {%0,%1,%2,%3};"
                : "+f"(d0), "+f"(d1), "+f"(d2), "+f"(d3)
                : "r"(af[s][0]), "r"(af[s][1]), "r"(af[s][2]), "r"(af[s][3]),
                  "r"(b0), "r"(b1));
        }

        s_lo += d0 + d1;  q_lo = fmaf(d0, d0, fmaf(d1, d1, q_lo));
        s_hi += d2 + d3;  q_hi = fmaf(d2, d2, fmaf(d3, d3, q_hi));

        float m0 = fmaxf(d0, d1);
        float m2 = fmaxf(d2, d3);
        m0 = fmaxf(m0, __shfl_xor_sync(0xffffffffu, m0, 2));
        m2 = fmaxf(m2, __shfl_xor_sync(0xffffffffu, m2, 2));
        if (t < 2) {
            int pr = 8 * bti + trow;
            int pc = 8 * btj + 2 * tq + t;
            __half* up = g_u1 + ((n * HP + pr) * HP + pc) * C1;
            up[g]     = __float2half(m0);
            up[g + 8] = __float2half(m2);
        }
    }

    s_lo += __shfl_xor_sync(0xffffffffu, s_lo, 1);
    s_lo += __shfl_xor_sync(0xffffffffu, s_lo, 2);
    q_lo += __shfl_xor_sync(0xffffffffu, q_lo, 1);
    q_lo += __shfl_xor_sync(0xffffffffu, q_lo, 2);
    s_hi += __shfl_xor_sync(0xffffffffu, s_hi, 1);
    s_hi += __shfl_xor_sync(0xffffffffu, s_hi, 2);
    q_hi += __shfl_xor_sync(0xffffffffu, q_hi, 1);
    q_hi += __shfl_xor_sync(0xffffffffu, q_hi, 2);
    if (t == 0) {
        atomicAdd(&sh_s[g], s_lo);     atomicAdd(&sh_q[g], q_lo);
        atomicAdd(&sh_s[g + 8], s_hi); atomicAdd(&sh_q[g + 8], q_hi);
    }
    __syncthreads();
    if (tid < C1) {
        int bin = blk & 31;
        atomicAdd(&g_part1[bin][tid][0], (double)sh_s[tid]);
        atomicAdd(&g_part1[bin][tid][1], (double)sh_q[tid]);
    }
}

// conv2(stride2,pad1) via HMMA (R13 exact form): K-step = one tap's 16 NHWC
// channels; BN1+ReLU in half2 registers; pad taps zeroed. Warp = 8 pixels.
__global__ void __launch_bounds__(128) k_conv2(const float* __restrict__ w,
                                               const float* __restrict__ g1,
                                               const float* __restrict__ b1) {
    __shared__ __align__(16) uint32_t wfragF[2 * 9 * 32 * 4]; // [m][tap][lane][r]
    __shared__ float sc1[C1], sh1[C1];
    __shared__ float s2s[C2], s2q[C2];

    int tid = threadIdx.x;
    if (tid < C1) {
        int c = tid;
        double s = 0.0, q = 0.0;
#pragma unroll
        for (int bb = 0; bb < 32; bb++) { s += g_part1[bb][c][0]; q += g_part1[bb][c][1]; }
        double mean = s / NPIX1;
        double var  = q / NPIX1 - mean * mean;
        float scale = g1[c] * (1.0f / sqrtf((float)var + BN_EPS));
        sc1[c] = scale;
        sh1[c] = b1[c] - (float)mean * scale;
    }
    if (tid < C2) { s2s[tid] = 0.f; s2q[tid] = 0.f; }

    // build per-lane A fragments: entry e = ((m*9+tap)*32+lane)*4 + r
    for (int e = tid; e < 2304; e += 128) {
        int r    = e & 3;
        int ln   = (e >> 2) & 31;
        int mt   = e >> 7;             // 0..17
        int tap  = mt % 9;
        int m    = mt / 9;
        int gg   = ln >> 2, tt = ln & 3;
        int row  = 16 * m + gg + ((r & 1) ? 8 : 0);
        int k0   = 2 * tt + ((r & 2) ? 8 : 0);
        __half2 h = __floats2half2_rn(w[row * 144 + k0 * 9 + tap],
                                      w[row * 144 + (k0 + 1) * 9 + tap]);
        wfragF[e] = *reinterpret_cast<uint32_t*>(&h);
    }
    __syncthreads();

    int lane = tid & 31;
    int warp = tid >> 5;
    int g = lane >> 2;
    int t = lane & 3;

    int tilebase = (blockIdx.x * 4 + warp) * 8;     // 8 pixels per warp
    int p   = tilebase + g;                          // this lane's pixel
    int n   = p / (H2 * W2);
    int rem = p - n * (H2 * W2);
    int ho  = rem / W2;
    int wo  = rem - ho * W2;

    // lane BN constants: channels (2t,2t+1) and (2t+8,2t+9)
    __half2 scA = __floats2half2_rn(sc1[2 * t],     sc1[2 * t + 1]);
    __half2 shA = __floats2half2_rn(sh1[2 * t],     sh1[2 * t + 1]);
    __half2 scB = __floats2half2_rn(sc1[2 * t + 8], sc1[2 * t + 9]);
    __half2 shB = __floats2half2_rn(sh1[2 * t + 8], sh1[2 * t + 9]);
    __half2 z2  = __float2half2_rn(0.f);

    float d0[4] = {0.f, 0.f, 0.f, 0.f};
    float d1m[4] = {0.f, 0.f, 0.f, 0.f};

#pragma unroll
    for (int ky = 0; ky < 3; ky++) {
        int row = 2 * ho - 1 + ky;                   // <= 55 always
        bool rok = (row >= 0);
        const uint32_t* rowp = reinterpret_cast<const uint32_t*>(
            g_u1 + ((n * HP + row) * HP) * C1);
#pragma unroll
        for (int kx = 0; kx < 3; kx++) {
            int col = 2 * wo - 1 + kx;               // <= 55 always
            uint32_t b0 = 0u, b1 = 0u;
            if (rok && col >= 0) {
                uint32_t v0 = rowp[col * 8 + t];
                uint32_t v1 = rowp[col * 8 + t + 4];
                __half2 h0 = __hmax2(__hfma2(*reinterpret_cast<__half2*>(&v0), scA, shA), z2);
                __half2 h1 = __hmax2(__hfma2(*reinterpret_cast<__half2*>(&v1), scB, shB), z2);
                b0 = *reinterpret_cast<uint32_t*>(&h0);
                b1 = *reinterpret_cast<uint32_t*>(&h1);
            }
            int tap = ky * 3 + kx;
            uint4 A0 = *reinterpret_cast<const uint4*>(&wfragF[(tap * 32 + lane) * 4]);
            uint4 A1 = *reinterpret_cast<const uint4*>(&wfragF[((9 + tap) * 32 + lane) * 4]);
            asm volatile(
                "mma.sync.aligned.m16n8k16.row.col.f32.f16.f16.f32 "
                "{%0,%1,%2,%3}, {%4,%5,%6,%7}, {%8,%9}, {%0,%1,%2,%3};"
                : "+f"(d0[0]), "+f"(d0[1]), "+f"(d0[2]), "+f"(d0[3])
                : "r"(A0.x), "r"(A0.y), "r"(A0.z), "r"(A0.w), "r"(b0), "r"(b1));
            asm volatile(
                "mma.sync.aligned.m16n8k16.row.col.f32.f16.f16.f32 "
                "{%0,%1,%2,%3}, {%4,%5,%6,%7}, {%8,%9}, {%0,%1,%2,%3};"
                : "+f"(d1m[0]), "+f"(d1m[1]), "+f"(d1m[2]), "+f"(d1m[3])
                : "r"(A1.x), "r"(A1.y), "r"(A1.z), "r"(A1.w), "r"(b0), "r"(b1));
        }
    }

    // store: lane owns out ch {g, g+8, g+16, g+24} at pixels tilebase+2t, +2t+1
    {
        __half* y0 = g_y2 + (long)(tilebase + 2 * t) * C2;
        __half* y1 = y0 + C2;
        y0[g]      = __float2half(d0[0]);  y1[g]      = __float2half(d0[1]);
        y0[g + 8]  = __float2half(d0[2]);  y1[g + 8]  = __float2half(d0[3]);
        y0[g + 16] = __float2half(d1m[0]); y1[g + 16] = __float2half(d1m[1]);
        y0[g + 24] = __float2half(d1m[2]); y1[g + 24] = __float2half(d1m[3]);
    }

    // BN2 stats: reduce over t lanes (bits 0,1), channels per (m, lo/hi)
#pragma unroll
    for (int m = 0; m < 2; m++) {
        const float* dd = (m == 0) ? d0 : d1m;
        float sl = dd[0] + dd[1];
        float ql = fmaf(dd[0], dd[0], dd[1] * dd[1]);
        float sh = dd[2] + dd[3];
        float qh = fmaf(dd[2], dd[2], dd[3] * dd[3]);
        sl += __shfl_xor_sync(0xffffffffu, sl, 1);
        sl += __shfl_xor_sync(0xffffffffu, sl, 2);
        ql += __shfl_xor_sync(0xffffffffu, ql, 1);
        ql += __shfl_xor_sync(0xffffffffu, ql, 2);
        sh += __shfl_xor_sync(0xffffffffu, sh, 1);
        sh += __shfl_xor_sync(0xffffffffu, sh, 2);
        qh += __shfl_xor_sync(0xffffffffu, qh, 1);
        qh += __shfl_xor_sync(0xffffffffu, qh, 2);
        if (t == 0) {
            atomicAdd(&s2s[16 * m + g], sl);     atomicAdd(&s2q[16 * m + g], ql);
            atomicAdd(&s2s[16 * m + g + 8], sh); atomicAdd(&s2q[16 * m + g + 8], qh);
        }
    }
    __syncthreads();
    if (tid < C2) {
        int bin = blockIdx.x & 15;
        atomicAdd(&g_part2[bin][tid][0], (double)s2s[tid]);
        atomicAdd(&g_part2[bin][tid][1], (double)s2q[tid]);
    }
}

// BN2+ReLU+avg+fc partials: 2 blocks/sample -> atomic into g_logit (R13 form)
__global__ void __launch_bounds__(256) k_final2(const float* __restrict__ g2,
                                                const float* __restrict__ b2,
                                                const float* __restrict__ fcw) {
    __shared__ float ssc[C2], ssh[C2], sw[C2];
    __shared__ float red[256];
    int tid = threadIdx.x;
    if (tid < C2) {
        double s = 0.0, q = 0.0;
#pragma unroll
        for (int bb = 0; bb < 16; bb++) { s += g_part2[bb][tid][0]; q += g_part2[bb][tid][1]; }
        double mean = s / NPIX2;
        double var  = q / NPIX2 - mean * mean;
        float scale = g2[tid] * (1.0f / sqrtf((float)var + BN_EPS));
        ssc[tid] = scale;
        ssh[tid] = b2[tid] - (float)mean * scale;
        sw[tid]  = fcw[tid];
    }
    __syncthreads();

    int cg = (tid & 3) * 8;
    float rsc[8], rsh[8], rw[8];
#pragma unroll
    for (int k = 0; k < 8; k++) { rsc[k] = ssc[cg + k]; rsh[k] = ssh[cg + k]; rw[k] = sw[cg + k]; }

    int n     = blockIdx.x >> 1;
    int chunk = blockIdx.x & 1;
    const uint4* p = reinterpret_cast<const uint4*>(g_y2 + n * H2 * W2 * C2);
    const int NV = H2 * W2 * C2 / 8;
    int start = chunk * (NV / 2);
    float acc = 0.f;
    for (int i = start + tid; i < start + NV / 2; i += 256) {
        float f[8];
        u4_to_f8(p[i], f);
#pragma unroll
        for (int k = 0; k < 8; k++) {
            float e = fmaxf(fmaf(rsc[k], f[k], rsh[k]), 0.f);
            acc = fmaf(rw[k], e, acc);
        }
    }
    red[tid] = acc;
    __syncthreads();
    for (int o = 128; o > 0; o >>= 1) {
        if (tid < o) red[tid] += red[tid + o];
        __syncthreads();
    }
    if (tid == 0) atomicAdd(&g_logit[n], red[0]);
}

// cos + output, THEN re-zero all accumulators for the next replay.
__global__ void k_coszero(const float* __restrict__ fcb, float* __restrict__ out) {
    int tid = threadIdx.x;
    if (tid < B) {
        float logit = g_logit[tid] / (float)(H2 * W2) + fcb[0];
        float pr = cosf(logit);
        out[2 * tid]     = pr;
        out[2 * tid + 1] = 1.f - pr;
    }
    __syncthreads();
    if (tid < B) g_logit[tid] = 0.f;
    double* p1 = &g_part1[0][0][0];        // 1024 doubles
    double* p2 = &g_part2[0][0][0];        // 512 doubles
    for (int i = tid; i < 32 * C1 * 2; i += 128) p1[i] = 0.0;
    for (int i = tid; i < 16 * C2 * 2; i += 128) p2[i] = 0.0;
}

// ---------------- launcher ----------------
extern "C" void kernel_launch(void* const* d_in, const int* in_sizes, int n_in,
                              void* d_out, int out_size) {
    const float* x    = (const float*)d_in[0];
    const float* c1w  = (const float*)d_in[1];
    const float* bn1g = (const float*)d_in[3];
    const float* bn1b = (const float*)d_in[4];
    const float* c2w  = (const float*)d_in[5];
    const float* bn2g = (const float*)d_in[7];
    const float* bn2b = (const float*)d_in[8];
    const float* fcw  = (const float*)d_in[9];
    const float* fcb  = (const float*)d_in[10];
    float* out = (float*)d_out;

    k_conv1pool<<<B * 49, 128>>>(x, c1w);                    // 6272 blocks
    k_conv2<<<(B * H2 * W2) / 32, 128>>>(c2w, bn1g, bn1b);   // 3136 blocks
    k_final2<<<B * 2, 256>>>(bn2g, bn2b, fcw);
    k_coszero<<<1, 128>>>(fcb, out);
}